// round 2
// baseline (speedup 1.0000x reference)
#include <cuda_runtime.h>
#include <cstdint>

// Problem constants (from reference): B=1, Z=1, X=Y=360, C=80
#define XDIM  360
#define YDIM  360
#define CDIM  80
#define CELLS (XDIM * YDIM)          // 129600
#define NP_MAX 2000000               // Np = 1*6*118*32*88 = 1,993,728

// Scratch: accumulation grid in (xy, c) layout => per-point channel writes are
// contiguous (coalesced atomics). 41.47 MB, fits in L2 (126 MB).
__device__ __align__(256) float g_scratch[CELLS * CDIM];
// Per-point cell index (or -1 if dropped). 8 MB.
__device__ __align__(256) int g_cell[NP_MAX];

// ---------------------------------------------------------------------------
// Kernel 1: zero the scratch accumulator (float4-wide).
// ---------------------------------------------------------------------------
__global__ void zero_kernel(int n4) {
    int i = blockIdx.x * blockDim.x + threadIdx.x;
    if (i < n4) {
        reinterpret_cast<float4*>(g_scratch)[i] = make_float4(0.f, 0.f, 0.f, 0.f);
    }
}

// ---------------------------------------------------------------------------
// Kernel 2: per-point voxel index.
// XLA's algebraic simplifier rewrites (v - lo) / DX into (v - lo) * (1/DX)
// with the reciprocal rounded once to f32. Replicate that exactly:
//   lo  = BX - DX/2 evaluated in f32  (== -54.0f, -54.0f, -10.0f)
//   r   = f32(1.0 / DX)               (rn-rounded reciprocal)
//   idx = floor((v - lo) * r)
// ---------------------------------------------------------------------------
__global__ void idx_kernel(const float* __restrict__ geom, int np) {
    int p = blockIdx.x * blockDim.x + threadIdx.x;
    if (p >= np) return;

    float gx = geom[3 * (size_t)p + 0];
    float gy = geom[3 * (size_t)p + 1];
    float gz = geom[3 * (size_t)p + 2];

    const float lox = -53.85f - 0.3f * 0.5f;   // -54.0f exactly (f32 arithmetic)
    const float loy = -53.85f - 0.3f * 0.5f;
    const float loz =   0.0f  - 20.0f * 0.5f;  // -10.0f

    const float rx = 1.0f / 0.3f;    // compile-time f32 rn reciprocal
    const float ry = 1.0f / 0.3f;
    const float rz = 1.0f / 20.0f;   // 0.05f, exact

    int xi = (int)floorf((gx - lox) * rx);
    int yi = (int)floorf((gy - loy) * ry);
    int zi = (int)floorf((gz - loz) * rz);

    bool kept = (xi >= 0) & (xi < XDIM) & (yi >= 0) & (yi < YDIM) &
                (zi >= 0) & (zi < 1);
    // Reference: idx = ((b*Z+zi)*X + xi)*Y + yi ; B=1, Z=1, zi=0 => xi*360+yi
    g_cell[p] = kept ? (xi * YDIM + yi) : -1;
}

// ---------------------------------------------------------------------------
// Kernel 3: scatter-add. 320 threads = 64 points/block, 5 slots/point,
// 16 floats (4x float4) per slot covers C=80. Warp-contiguous feats loads and
// warp-contiguous vector reds (red.global.add.v4.f32, sm_90+).
// ---------------------------------------------------------------------------
__device__ __forceinline__ void red4(float* addr, float4 v) {
    asm volatile("red.global.add.v4.f32 [%0], {%1, %2, %3, %4};"
                 :: "l"(addr), "f"(v.x), "f"(v.y), "f"(v.z), "f"(v.w)
                 : "memory");
}

__global__ void __launch_bounds__(320) scatter_kernel(
    const float* __restrict__ feats, int np)
{
    int lp   = threadIdx.x / 5;     // local point 0..63
    int slot = threadIdx.x % 5;     // 0..4
    int p = blockIdx.x * 64 + lp;
    if (p >= np) return;

    int cell = g_cell[p];
    if (cell < 0) return;

    const float4* f =
        reinterpret_cast<const float4*>(feats + (size_t)p * CDIM + slot * 16);
    float4 a = f[0];
    float4 b = f[1];
    float4 c = f[2];
    float4 d = f[3];

    float* o = g_scratch + (size_t)cell * CDIM + slot * 16;
    red4(o + 0,  a);
    red4(o + 4,  b);
    red4(o + 8,  c);
    red4(o + 12, d);
}

// ---------------------------------------------------------------------------
// Kernel 4: transpose scratch (xy, c) -> out (c, xy). 32x32 smem tile.
// out[c*129600 + xy] = scratch[xy*80 + c]. Fully overwrites d_out.
// ---------------------------------------------------------------------------
__global__ void transpose_kernel(float* __restrict__ out) {
    __shared__ float s[32][33];
    int xy0 = blockIdx.x * 32;          // 129600 / 32 = 4050 exact
    int c0  = blockIdx.y * 32;          // c tiles: 0, 32, 64 (last partial)
    int tx = threadIdx.x, ty = threadIdx.y;

    int c = c0 + tx;
    if (c < CDIM) {
        s[ty][tx] = g_scratch[(size_t)(xy0 + ty) * CDIM + c];
    }
    __syncthreads();

    int co = c0 + ty;
    if (co < CDIM) {
        out[(size_t)co * CELLS + xy0 + tx] = s[tx][ty];
    }
}

// ---------------------------------------------------------------------------
// Launch
// ---------------------------------------------------------------------------
extern "C" void kernel_launch(void* const* d_in, const int* in_sizes, int n_in,
                              void* d_out, int out_size)
{
    const float* geom  = (const float*)d_in[0];
    const float* feats = (const float*)d_in[1];
    float* out = (float*)d_out;

    int np = in_sizes[0] / 3;   // 1,993,728

    // 1) zero accumulator
    int n4 = (CELLS * CDIM) / 4;
    zero_kernel<<<(n4 + 255) / 256, 256>>>(n4);

    // 2) per-point cell indices
    idx_kernel<<<(np + 255) / 256, 256>>>(geom, np);

    // 3) scatter-add (64 points per 320-thread block)
    int nblk = (np + 63) / 64;
    scatter_kernel<<<nblk, 320>>>(feats, np);

    // 4) transpose into final (c, x, y) layout
    dim3 tb(32, 32);
    dim3 tg(CELLS / 32, (CDIM + 31) / 32);
    transpose_kernel<<<tg, tb>>>(out);
}

// round 3
// speedup vs baseline: 1.3488x; 1.3488x over previous
#include <cuda_runtime.h>
#include <cstdint>

// Problem constants: B=1, Z=1, X=Y=360, C=80, Np=1,993,728
#define XDIM  360
#define YDIM  360
#define CDIM  80
#define CELLS (XDIM * YDIM)          // 129600 = 4050 * 32
#define NP_MAX 2000000
#define SCAN_NB 127                  // ceil(129600/1024)

__device__ __align__(256) int g_cell[NP_MAX];      // cell per point, -1 dropped
__device__ __align__(256) int g_count[CELLS];      // histogram
__device__ __align__(256) int g_offset[CELLS];     // exclusive scan
__device__ __align__(256) int g_cursor[CELLS];     // reorder cursors
__device__ __align__(256) int g_pid[NP_MAX];       // point ids sorted by cell
__device__ int g_blocksum[SCAN_NB];

// ---------------------------------------------------------------------------
// 1) zero histogram counters
// ---------------------------------------------------------------------------
__global__ void zero_counts_kernel() {
    int i = blockIdx.x * blockDim.x + threadIdx.x;
    if (i < CELLS) g_count[i] = 0;
}

// ---------------------------------------------------------------------------
// 2) cell index + histogram.
// XLA rewrites (v-lo)/DX into (v-lo)*(1/DX) with rn-rounded f32 reciprocal —
// replicate exactly (validated R2: rel_err 3.8e-8).
// ---------------------------------------------------------------------------
__global__ void idx_hist_kernel(const float* __restrict__ geom, int np) {
    int p = blockIdx.x * blockDim.x + threadIdx.x;
    if (p >= np) return;

    float gx = geom[3 * (size_t)p + 0];
    float gy = geom[3 * (size_t)p + 1];
    float gz = geom[3 * (size_t)p + 2];

    const float lox = -53.85f - 0.3f * 0.5f;   // -54.0f in f32
    const float loz =   0.0f  - 20.0f * 0.5f;  // -10.0f
    const float rxy = 1.0f / 0.3f;             // rn f32 reciprocal
    const float rz  = 1.0f / 20.0f;            // exact

    int xi = (int)floorf((gx - lox) * rxy);
    int yi = (int)floorf((gy - lox) * rxy);
    int zi = (int)floorf((gz - loz) * rz);

    bool kept = (xi >= 0) & (xi < XDIM) & (yi >= 0) & (yi < YDIM) &
                (zi >= 0) & (zi < 1);
    int cell = kept ? (xi * YDIM + yi) : -1;
    g_cell[p] = cell;
    if (cell >= 0) atomicAdd(&g_count[cell], 1);
}

// ---------------------------------------------------------------------------
// 3a) per-block exclusive scan of counts (1024 elems/block)
// ---------------------------------------------------------------------------
__global__ __launch_bounds__(1024) void scan_block_kernel() {
    __shared__ int warpsum[32];
    int t = threadIdx.x;
    int gid = blockIdx.x * 1024 + t;
    int v = (gid < CELLS) ? g_count[gid] : 0;

    int x = v;
    #pragma unroll
    for (int d = 1; d < 32; d <<= 1) {
        int y = __shfl_up_sync(0xFFFFFFFFu, x, d);
        if ((t & 31) >= d) x += y;
    }
    if ((t & 31) == 31) warpsum[t >> 5] = x;
    __syncthreads();
    if (t < 32) {
        int w = warpsum[t];
        #pragma unroll
        for (int d = 1; d < 32; d <<= 1) {
            int y = __shfl_up_sync(0xFFFFFFFFu, w, d);
            if (t >= d) w += y;
        }
        warpsum[t] = w;
    }
    __syncthreads();
    int base = (t >= 32) ? warpsum[(t >> 5) - 1] : 0;
    int incl = x + base;
    if (gid < CELLS) g_offset[gid] = incl - v;       // exclusive
    if (t == 1023) g_blocksum[blockIdx.x] = incl;    // block total
}

// ---------------------------------------------------------------------------
// 3b) add block bases, materialize offsets + cursors
// ---------------------------------------------------------------------------
__global__ __launch_bounds__(1024) void scan_add_kernel() {
    __shared__ int bs[SCAN_NB];
    int t = threadIdx.x, b = blockIdx.x;
    if (t < SCAN_NB) bs[t] = g_blocksum[t];
    __syncthreads();
    int base = 0;
    for (int j = 0; j < b; j++) base += bs[j];       // smem broadcast loop
    int gid = b * 1024 + t;
    if (gid < CELLS) {
        int o = g_offset[gid] + base;
        g_offset[gid] = o;
        g_cursor[gid] = o;
    }
}

// ---------------------------------------------------------------------------
// 4) reorder: bucket point ids by cell
// ---------------------------------------------------------------------------
__global__ void reorder_kernel(int np) {
    int p = blockIdx.x * blockDim.x + threadIdx.x;
    if (p >= np) return;
    int cell = g_cell[p];
    if (cell < 0) return;
    int pos = atomicAdd(&g_cursor[cell], 1);
    g_pid[pos] = p;
}

// ---------------------------------------------------------------------------
// 5) gather: warp per cell; lanes 0..19 own one float4 of C=80.
//    Block = 32 warps = 32 consecutive xy cells. Epilogue transposes through
//    smem and writes out[c][xy] with 128B-coalesced stores. No float atomics.
// ---------------------------------------------------------------------------
__global__ __launch_bounds__(1024) void gather_kernel(
    const float* __restrict__ feats, float* __restrict__ out)
{
    __shared__ float s[32][81];   // [local cell][channel], pad: stride 81 (odd)

    int lane = threadIdx.x & 31;
    int wid  = threadIdx.x >> 5;            // local cell 0..31
    int cell = blockIdx.x * 32 + wid;       // CELLS = 4050*32 exact

    int start = g_offset[cell];
    int cnt   = g_count[cell];

    if (lane < 20) {
        const float4* f4 = reinterpret_cast<const float4*>(feats);
        float4 acc = make_float4(0.f, 0.f, 0.f, 0.f);
        int j = 0;
        for (; j + 1 < cnt; j += 2) {
            int p0 = g_pid[start + j];
            int p1 = g_pid[start + j + 1];
            float4 v0 = f4[(size_t)p0 * 20 + lane];
            float4 v1 = f4[(size_t)p1 * 20 + lane];
            acc.x += v0.x; acc.y += v0.y; acc.z += v0.z; acc.w += v0.w;
            acc.x += v1.x; acc.y += v1.y; acc.z += v1.z; acc.w += v1.w;
        }
        if (j < cnt) {
            int p0 = g_pid[start + j];
            float4 v0 = f4[(size_t)p0 * 20 + lane];
            acc.x += v0.x; acc.y += v0.y; acc.z += v0.z; acc.w += v0.w;
        }
        int c = 4 * lane;
        s[wid][c + 0] = acc.x;
        s[wid][c + 1] = acc.y;
        s[wid][c + 2] = acc.z;
        s[wid][c + 3] = acc.w;
    }
    __syncthreads();

    // write out: 80 c x 32 xy = 2560 floats; warp covers 32 consecutive xy
    int xy0 = blockIdx.x * 32;
    #pragma unroll
    for (int r = 0; r < 3; r++) {
        int linear = r * 1024 + threadIdx.x;
        if (linear < CDIM * 32) {
            int c = linear >> 5;          // channel
            int x = linear & 31;          // local xy
            out[(size_t)c * CELLS + xy0 + x] = s[x][c];  // stride 81: no bank conflicts
        }
    }
}

// ---------------------------------------------------------------------------
// Launch
// ---------------------------------------------------------------------------
extern "C" void kernel_launch(void* const* d_in, const int* in_sizes, int n_in,
                              void* d_out, int out_size)
{
    const float* geom  = (const float*)d_in[0];
    const float* feats = (const float*)d_in[1];
    float* out = (float*)d_out;

    int np = in_sizes[0] / 3;   // 1,993,728

    zero_counts_kernel<<<(CELLS + 255) / 256, 256>>>();
    idx_hist_kernel<<<(np + 255) / 256, 256>>>(geom, np);
    scan_block_kernel<<<SCAN_NB, 1024>>>();
    scan_add_kernel<<<SCAN_NB, 1024>>>();
    reorder_kernel<<<(np + 255) / 256, 256>>>(np);
    gather_kernel<<<CELLS / 32, 1024>>>(feats, out);
}